// round 3
// baseline (speedup 1.0000x reference)
#include <cuda_runtime.h>
#include <cstdint>

// LSTM cell: B=8192, IN=H=1024. gates[B,4096] = x@Wi + h@Wh + bi + bh,
// then per-element sigmoid/tanh epilogue producing h_[B,1024], c_[B,1024].
// Output buffer = [h_ ; c_] (concatenated, 2*8192*1024 floats).

#define BDIM 8192
#define HDIM 1024
#define NG   4096

#define TM 128    // CTA batch-rows
#define TJ 32     // hidden units per CTA (MMA N = 4 gates * 32 = 128)
#define TK 32     // K per pipeline chunk
#define NCH 64    // total K = 2048 -> 64 chunks (32 for x/Wi, 32 for h/Wh)

#define AS_STRIDE 36     // floats per A SMEM row (32 + pad, conflict-free)
#define BS_STRIDE 136    // floats per B SMEM row (128 + pad, conflict-free)
#define AS_BUF (128 * AS_STRIDE)   // 4608 floats
#define BS_BUF (32 * BS_STRIDE)    // 4352 floats
#define SMEM_FLOATS (2 * AS_BUF + 2 * BS_BUF)   // 17920 floats = 71680 bytes

__device__ __forceinline__ uint32_t smem_u32(const void* p) {
    uint32_t a;
    asm("{ .reg .u64 t; cvta.to.shared.u64 t, %1; cvt.u32.u64 %0, t; }"
        : "=r"(a) : "l"(p));
    return a;
}

__device__ __forceinline__ void cp16(uint32_t dst, const void* src) {
    asm volatile("cp.async.cg.shared.global [%0], [%1], 16;"
                 :: "r"(dst), "l"(src) : "memory");
}

__device__ __forceinline__ uint32_t f2tf32(float x) {
    uint32_t u;
    asm("cvt.rna.tf32.f32 %0, %1;" : "=r"(u) : "f"(x));
    return u;
}

// D(16x8) += A(16x8, tf32) * B(8x8, tf32)
__device__ __forceinline__ void mma8(float* c, const uint32_t* a, const uint32_t* b) {
    asm volatile(
        "mma.sync.aligned.m16n8k8.row.col.f32.tf32.tf32.f32 "
        "{%0,%1,%2,%3}, {%4,%5,%6,%7}, {%8,%9}, {%0,%1,%2,%3};"
        : "+f"(c[0]), "+f"(c[1]), "+f"(c[2]), "+f"(c[3])
        : "r"(a[0]), "r"(a[1]), "r"(a[2]), "r"(a[3]), "r"(b[0]), "r"(b[1]));
}

__global__ void __launch_bounds__(256, 2)
lstm_kernel(const float* __restrict__ x,  const float* __restrict__ h,
            const float* __restrict__ c,  const float* __restrict__ Wi,
            const float* __restrict__ bi, const float* __restrict__ Wh,
            const float* __restrict__ bh, float* __restrict__ out)
{
    extern __shared__ float smem[];
    float* As = smem;                 // 2 buffers: [128][AS_STRIDE]
    float* Bs = smem + 2 * AS_BUF;    // 2 buffers: [32][BS_STRIDE] (n = g*32 + jj)
    const uint32_t as_u = smem_u32(As);
    const uint32_t bs_u = smem_u32(Bs);

    const int tid  = threadIdx.x;
    const int lane = tid & 31;
    const int wid  = tid >> 5;
    const int wm   = wid >> 2;          // 0..1  (warp M: 64 rows each)
    const int wn   = wid & 3;           // 0..3  (warp j-subrange: 8 cols each)
    const int gid  = lane >> 2;         // 0..7
    const int t4   = lane & 3;          // 0..3
    const int m0   = blockIdx.y * TM;
    const int j0   = blockIdx.x * TJ;

    // Accumulators: acc[mtile 0..3][gate 0..3][reg 0..3]
    float acc[4][4][4];
#pragma unroll
    for (int a = 0; a < 4; a++)
#pragma unroll
        for (int g = 0; g < 4; g++)
#pragma unroll
            for (int r = 0; r < 4; r++) acc[a][g][r] = 0.0f;

    // ---- async tile loader (256 threads; 4 x 16B each per tile) ----
#define LOAD_CHUNK(cc, buf) do {                                                \
    const float* Ap_ = ((cc) < 32) ? x : h;                                     \
    const float* Bp_ = ((cc) < 32) ? Wi : Wh;                                   \
    const int kloc_ = ((cc) & 31) * TK;                                         \
    _Pragma("unroll")                                                           \
    for (int i_ = 0; i_ < 4; i_++) {                                            \
        int q_ = tid + i_ * 256;                                                \
        int row_ = q_ >> 3, seg_ = q_ & 7;                                      \
        cp16(as_u + 4u * ((buf) * AS_BUF + row_ * AS_STRIDE + seg_ * 4),        \
             Ap_ + (size_t)(m0 + row_) * HDIM + kloc_ + seg_ * 4);              \
    }                                                                           \
    _Pragma("unroll")                                                           \
    for (int i_ = 0; i_ < 4; i_++) {                                            \
        int q_ = tid + i_ * 256;                                                \
        int kr_ = q_ >> 5, seg_ = q_ & 31;                                      \
        int g_ = seg_ >> 3, sub_ = seg_ & 7;                                    \
        cp16(bs_u + 4u * ((buf) * BS_BUF + kr_ * BS_STRIDE + g_ * 32 + sub_ * 4),\
             Bp_ + (size_t)(kloc_ + kr_) * NG + g_ * HDIM + j0 + sub_ * 4);     \
    }                                                                           \
    asm volatile("cp.async.commit_group;" ::: "memory");                        \
} while (0)

    LOAD_CHUNK(0, 0);

    for (int cc = 0; cc < NCH; ++cc) {
        const int buf = cc & 1;
        if (cc + 1 < NCH) {
            LOAD_CHUNK(cc + 1, buf ^ 1);
            asm volatile("cp.async.wait_group 1;" ::: "memory");
        } else {
            asm volatile("cp.async.wait_group 0;" ::: "memory");
        }
        __syncthreads();

        const float* Aw = As + buf * AS_BUF + (wm * 64 + gid) * AS_STRIDE;
        const float* Bw = Bs + buf * BS_BUF + wn * 8 + gid;

#pragma unroll
        for (int kt = 0; kt < 4; kt++) {
            uint32_t af[4][4], bf[4][2];
#pragma unroll
            for (int mt = 0; mt < 4; mt++) {
                const float* p = Aw + mt * (16 * AS_STRIDE) + kt * 8 + t4;
                af[mt][0] = f2tf32(p[0]);
                af[mt][1] = f2tf32(p[8 * AS_STRIDE]);
                af[mt][2] = f2tf32(p[4]);
                af[mt][3] = f2tf32(p[8 * AS_STRIDE + 4]);
            }
#pragma unroll
            for (int g = 0; g < 4; g++) {
                const float* p = Bw + (kt * 8 + t4) * BS_STRIDE + g * 32;
                bf[g][0] = f2tf32(p[0]);
                bf[g][1] = f2tf32(p[4 * BS_STRIDE]);
            }
#pragma unroll
            for (int mt = 0; mt < 4; mt++)
#pragma unroll
                for (int g = 0; g < 4; g++)
                    mma8(acc[mt][g], af[mt], bf[g]);
        }
        __syncthreads();
    }
#undef LOAD_CHUNK

    // ---- fused LSTM epilogue: all 4 gates for (m, j) live in this thread ----
    const int jl = wn * 8 + 2 * t4;       // local j (even)
    const int jg = j0 + jl;               // global hidden index

    float bsum[4][2];
#pragma unroll
    for (int g = 0; g < 4; g++) {
        int o = g * HDIM + jg;
        bsum[g][0] = bi[o] + bh[o];
        bsum[g][1] = bi[o + 1] + bh[o + 1];
    }

    float* outh = out;
    float* outc = out + (size_t)BDIM * HDIM;

#pragma unroll
    for (int mt = 0; mt < 4; mt++) {
#pragma unroll
        for (int rh = 0; rh < 2; rh++) {   // row groups gid, gid+8
            const int r = m0 + wm * 64 + mt * 16 + gid + rh * 8;
            const size_t base = (size_t)r * HDIM + jg;
            const float2 cv = *(const float2*)(c + base);
            float hv[2], cn2[2];
#pragma unroll
            for (int e = 0; e < 2; e++) {  // columns jg, jg+1
                const int ri = rh * 2 + e; // reg: {0,1}=row gid, {2,3}=row gid+8
                float gI = acc[mt][0][ri] + bsum[0][e];
                float gF = acc[mt][1][ri] + bsum[1][e];
                float gG = acc[mt][2][ri] + bsum[2][e];
                float gO = acc[mt][3][ri] + bsum[3][e];
                float I = 1.0f / (1.0f + __expf(-gI));
                float F = 1.0f / (1.0f + __expf(-gF));
                float G = tanhf(gG);
                float O = 1.0f / (1.0f + __expf(-gO));
                float cprev = e ? cv.y : cv.x;
                float cn = fmaf(F, cprev, I * G);
                float hn = O * tanhf(cn);
                hv[e] = hn;
                cn2[e] = cn;
            }
            *(float2*)(outh + base) = make_float2(hv[0], hv[1]);
            *(float2*)(outc + base) = make_float2(cn2[0], cn2[1]);
        }
    }
}

extern "C" void kernel_launch(void* const* d_in, const int* in_sizes, int n_in,
                              void* d_out, int out_size) {
    const float* x  = (const float*)d_in[0];
    const float* h  = (const float*)d_in[1];
    const float* c  = (const float*)d_in[2];
    const float* Wi = (const float*)d_in[3];
    const float* bi = (const float*)d_in[4];
    const float* Wh = (const float*)d_in[5];
    const float* bh = (const float*)d_in[6];
    float* out = (float*)d_out;

    const int smem_bytes = SMEM_FLOATS * (int)sizeof(float);   // 71680
    cudaFuncSetAttribute(lstm_kernel,
                         cudaFuncAttributeMaxDynamicSharedMemorySize, smem_bytes);
    dim3 grid(HDIM / TJ, BDIM / TM);   // (32, 64) = 2048 CTAs
    lstm_kernel<<<grid, 256, smem_bytes>>>(x, h, c, Wi, bi, Wh, bh, out);
}

// round 6
// speedup vs baseline: 1.0393x; 1.0393x over previous
#include <cuda_runtime.h>
#include <cstdint>

// ============================================================================
// LSTM cell: B=8192, IN=H=1024. gates[B,4096] = x@Wi + h@Wh + bi + bh,
// then sigmoid/tanh epilogue -> h_[B,1024], c_[B,1024]. Output = [h_ ; c_].
//
// Strategy (build target is compute_100 -> tcgen05 PTX unavailable):
//   legacy mma.sync tf32 path, but with all in-loop cvt.rna.tf32 removed by
//   pre-rounding x/h/Wi/Wh into tf32-representable fp32 scratch once, and a
//   3-stage cp.async pipeline. Gate-gathered tiles keep the epilogue fused.
// ============================================================================

#define BDIM 8192
#define HDIM 1024
#define NG   4096

#define TM 128    // CTA batch-rows
#define TJ 32     // hidden units per CTA (MMA N = 4 gates * 32 = 128)
#define TK 32     // K per pipeline chunk
#define NCH 64    // total K = 2048 -> 64 chunks (32 for x/Wi, 32 for h/Wh)
#define NSTG 3    // cp.async pipeline stages

#define AS_STRIDE 36     // floats per A SMEM row (32 + pad, conflict-free)
#define BS_STRIDE 136    // floats per B SMEM row (128 + pad, conflict-free)
#define AS_BUF (128 * AS_STRIDE)   // 4608 floats
#define BS_BUF (32 * BS_STRIDE)    // 4352 floats
#define SMEM_FLOATS (NSTG * (AS_BUF + BS_BUF))   // 26880 floats = 107520 B

// ---- 96 MB scratch: tf32-rounded copies (same layouts as the originals) ----
__device__ float g_xr[(size_t)BDIM * HDIM];    // 32 MB
__device__ float g_hr[(size_t)BDIM * HDIM];    // 32 MB
__device__ float g_wir[(size_t)HDIM * NG];     // 16 MB
__device__ float g_whr[(size_t)HDIM * NG];     // 16 MB

__device__ __forceinline__ uint32_t smem_u32(const void* p) {
    uint32_t a;
    asm("{ .reg .u64 t; cvta.to.shared.u64 t, %1; cvt.u32.u64 %0, t; }"
        : "=r"(a) : "l"(p));
    return a;
}

__device__ __forceinline__ void cp16(uint32_t dst, const void* src) {
    asm volatile("cp.async.cg.shared.global [%0], [%1], 16;"
                 :: "r"(dst), "l"(src) : "memory");
}

__device__ __forceinline__ float rna_tf32(float x) {
    uint32_t u;
    asm("cvt.rna.tf32.f32 %0, %1;" : "=r"(u) : "f"(x));
    return __uint_as_float(u);
}

// D(16x8) += A(16x8, tf32) * B(8x8, tf32)
__device__ __forceinline__ void mma8(float* c, const uint32_t* a, const uint32_t* b) {
    asm volatile(
        "mma.sync.aligned.m16n8k8.row.col.f32.tf32.tf32.f32 "
        "{%0,%1,%2,%3}, {%4,%5,%6,%7}, {%8,%9}, {%0,%1,%2,%3};"
        : "+f"(c[0]), "+f"(c[1]), "+f"(c[2]), "+f"(c[3])
        : "r"(a[0]), "r"(a[1]), "r"(a[2]), "r"(a[3]), "r"(b[0]), "r"(b[1]));
}

// ---------------------------------------------------------------------------
// Kernel 0: tf32-round a tensor (values become exactly tf32-representable,
// so feeding raw bits to mma.tf32 later is lossless truncation).
// ---------------------------------------------------------------------------
__global__ void __launch_bounds__(256)
round_kernel(const float4* __restrict__ src, float4* __restrict__ dst, int n4) {
    int i = blockIdx.x * blockDim.x + threadIdx.x;
    int stride = gridDim.x * blockDim.x;
    for (; i < n4; i += stride) {
        float4 v = src[i];
        v.x = rna_tf32(v.x); v.y = rna_tf32(v.y);
        v.z = rna_tf32(v.z); v.w = rna_tf32(v.w);
        dst[i] = v;
    }
}

// ---------------------------------------------------------------------------
// Main kernel: fused GEMM (mma.sync tf32) + LSTM epilogue
// ---------------------------------------------------------------------------
__global__ void __launch_bounds__(256, 2)
lstm_kernel(const float* __restrict__ x,  const float* __restrict__ h,
            const float* __restrict__ c,  const float* __restrict__ Wi,
            const float* __restrict__ bi, const float* __restrict__ Wh,
            const float* __restrict__ bh, float* __restrict__ out)
{
    extern __shared__ float smem[];
    float* As = smem;                    // NSTG buffers: [128][AS_STRIDE]
    float* Bs = smem + NSTG * AS_BUF;    // NSTG buffers: [32][BS_STRIDE]
    const uint32_t as_u = smem_u32(As);
    const uint32_t bs_u = smem_u32(Bs);

    const int tid  = threadIdx.x;
    const int lane = tid & 31;
    const int wid  = tid >> 5;
    const int wm   = wid >> 2;          // 0..1  (warp M: 64 rows each)
    const int wn   = wid & 3;           // 0..3  (warp j-subrange: 8 cols each)
    const int gid  = lane >> 2;         // 0..7
    const int t4   = lane & 3;          // 0..3
    const int m0   = blockIdx.y * TM;
    const int j0   = blockIdx.x * TJ;

    // Accumulators: acc[mtile 0..3][gate 0..3][reg 0..3]
    float acc[4][4][4];
#pragma unroll
    for (int a = 0; a < 4; a++)
#pragma unroll
        for (int g = 0; g < 4; g++)
#pragma unroll
            for (int r = 0; r < 4; r++) acc[a][g][r] = 0.0f;

    // ---- async tile loader (256 threads; 4 x 16B each per tile) ----
#define LOAD_CHUNK(cc, buf) do {                                                \
    const float* Ap_ = ((cc) < 32) ? x : h;                                     \
    const float* Bp_ = ((cc) < 32) ? Wi : Wh;                                   \
    const int kloc_ = ((cc) & 31) * TK;                                         \
    _Pragma("unroll")                                                           \
    for (int i_ = 0; i_ < 4; i_++) {                                            \
        int q_ = tid + i_ * 256;                                                \
        int row_ = q_ >> 3, seg_ = q_ & 7;                                      \
        cp16(as_u + 4u * ((buf) * AS_BUF + row_ * AS_STRIDE + seg_ * 4),        \
             Ap_ + (size_t)(m0 + row_) * HDIM + kloc_ + seg_ * 4);              \
    }                                                                           \
    _Pragma("unroll")                                                           \
    for (int i_ = 0; i_ < 4; i_++) {                                            \
        int q_ = tid + i_ * 256;                                                \
        int kr_ = q_ >> 5, seg_ = q_ & 31;                                      \
        int g_ = seg_ >> 3, sub_ = seg_ & 7;                                    \
        cp16(bs_u + 4u * ((buf) * BS_BUF + kr_ * BS_STRIDE + g_ * 32 + sub_ * 4),\
             Bp_ + (size_t)(kloc_ + kr_) * NG + g_ * HDIM + j0 + sub_ * 4);     \
    }                                                                           \
    asm volatile("cp.async.commit_group;" ::: "memory");                        \
} while (0)

    // prologue: prefetch chunks 0 and 1
    LOAD_CHUNK(0, 0);
    LOAD_CHUNK(1, 1);

    for (int cc = 0; cc < NCH; ++cc) {
        const int buf = cc % NSTG;
        // prefetch chunk cc+2 into the buffer freed at iteration cc-1
        if (cc + 2 < NCH) {
            int nb = (cc + 2) % NSTG;
            LOAD_CHUNK(cc + 2, nb);
            asm volatile("cp.async.wait_group 2;" ::: "memory");
        } else if (cc + 1 < NCH) {
            asm volatile("cp.async.wait_group 1;" ::: "memory");
        } else {
            asm volatile("cp.async.wait_group 0;" ::: "memory");
        }
        __syncthreads();

        const float* Aw = As + buf * AS_BUF + (wm * 64 + gid) * AS_STRIDE;
        const float* Bw = Bs + buf * BS_BUF + wn * 8 + gid;

#pragma unroll
        for (int kt = 0; kt < 4; kt++) {
            uint32_t af[4][4], bf[4][2];
#pragma unroll
            for (int mt = 0; mt < 4; mt++) {
                const float* p = Aw + mt * (16 * AS_STRIDE) + kt * 8 + t4;
                af[mt][0] = __float_as_uint(p[0]);
                af[mt][1] = __float_as_uint(p[8 * AS_STRIDE]);
                af[mt][2] = __float_as_uint(p[4]);
                af[mt][3] = __float_as_uint(p[8 * AS_STRIDE + 4]);
            }
#pragma unroll
            for (int g = 0; g < 4; g++) {
                const float* p = Bw + (kt * 8 + t4) * BS_STRIDE + g * 32;
                bf[g][0] = __float_as_uint(p[0]);
                bf[g][1] = __float_as_uint(p[4 * BS_STRIDE]);
            }
#pragma unroll
            for (int mt = 0; mt < 4; mt++)
#pragma unroll
                for (int g = 0; g < 4; g++)
                    mma8(acc[mt][g], af[mt], bf[g]);
        }
        __syncthreads();
    }
#undef LOAD_CHUNK

    // ---- fused LSTM epilogue: all 4 gates for (m, j) live in this thread ----
    const int jl = wn * 8 + 2 * t4;       // local j (even)
    const int jg = j0 + jl;               // global hidden index

    float bsum[4][2];
#pragma unroll
    for (int g = 0; g < 4; g++) {
        int o = g * HDIM + jg;
        bsum[g][0] = bi[o] + bh[o];
        bsum[g][1] = bi[o + 1] + bh[o + 1];
    }

    float* outh = out;
    float* outc = out + (size_t)BDIM * HDIM;

#pragma unroll
    for (int mt = 0; mt < 4; mt++) {
#pragma unroll
        for (int rh = 0; rh < 2; rh++) {   // row groups gid, gid+8
            const int r = m0 + wm * 64 + mt * 16 + gid + rh * 8;
            const size_t base = (size_t)r * HDIM + jg;
            const float2 cv = *(const float2*)(c + base);
            float hv[2], cn2[2];
#pragma unroll
            for (int e = 0; e < 2; e++) {  // columns jg, jg+1
                const int ri = rh * 2 + e; // reg: {0,1}=row gid, {2,3}=row gid+8
                float gI = acc[mt][0][ri] + bsum[0][e];
                float gF = acc[mt][1][ri] + bsum[1][e];
                float gG = acc[mt][2][ri] + bsum[2][e];
                float gO = acc[mt][3][ri] + bsum[3][e];
                float I = 1.0f / (1.0f + __expf(-gI));
                float F = 1.0f / (1.0f + __expf(-gF));
                float G = tanhf(gG);
                float O = 1.0f / (1.0f + __expf(-gO));
                float cprev = e ? cv.y : cv.x;
                float cn = fmaf(F, cprev, I * G);
                float hn = O * tanhf(cn);
                hv[e] = hn;
                cn2[e] = cn;
            }
            *(float2*)(outh + base) = make_float2(hv[0], hv[1]);
            *(float2*)(outc + base) = make_float2(cn2[0], cn2[1]);
        }
    }
}

extern "C" void kernel_launch(void* const* d_in, const int* in_sizes, int n_in,
                              void* d_out, int out_size) {
    const float* x  = (const float*)d_in[0];
    const float* h  = (const float*)d_in[1];
    const float* c  = (const float*)d_in[2];
    const float* Wi = (const float*)d_in[3];
    const float* bi = (const float*)d_in[4];
    const float* Wh = (const float*)d_in[5];
    const float* bh = (const float*)d_in[6];
    float* out = (float*)d_out;

    // scratch pointers
    void *pxr, *phr, *pwir, *pwhr;
    cudaGetSymbolAddress(&pxr,  g_xr);
    cudaGetSymbolAddress(&phr,  g_hr);
    cudaGetSymbolAddress(&pwir, g_wir);
    cudaGetSymbolAddress(&pwhr, g_whr);

    // 1) tf32-round inputs into scratch (4 small vectorized passes)
    const int n4_xh = (BDIM * HDIM) / 4;     // 2,097,152
    const int n4_w  = (HDIM * NG) / 4;       // 1,048,576
    round_kernel<<<2048, 256>>>((const float4*)x,  (float4*)pxr,  n4_xh);
    round_kernel<<<2048, 256>>>((const float4*)h,  (float4*)phr,  n4_xh);
    round_kernel<<<2048, 256>>>((const float4*)Wi, (float4*)pwir, n4_w);
    round_kernel<<<2048, 256>>>((const float4*)Wh, (float4*)pwhr, n4_w);

    // 2) fused GEMM + LSTM epilogue on the rounded copies
    const int smem_bytes = SMEM_FLOATS * (int)sizeof(float);   // 107520
    cudaFuncSetAttribute(lstm_kernel,
                         cudaFuncAttributeMaxDynamicSharedMemorySize, smem_bytes);
    dim3 grid(HDIM / TJ, BDIM / TM);   // (32, 64) = 2048 CTAs
    lstm_kernel<<<grid, 256, smem_bytes>>>((const float*)pxr, (const float*)phr,
                                           c, (const float*)pwir, bi,
                                           (const float*)pwhr, bh, out);
}